// round 4
// baseline (speedup 1.0000x reference)
#include <cuda_runtime.h>
#include <cstdint>

// Problem constants (all shapes fixed by setup_inputs)
#define B_WIN   4096
#define NTOK    49
#define C_DIM   192
#define NHEAD   6
#define DHEAD   32
#define NWIN    64
#define M_TOTAL (B_WIN * NTOK)     // 200704 = 128 * 1568
#define QKV_N   (3 * C_DIM)        // 576

// Scratch: __device__ globals (allocation-guard-safe)
__device__ float g_qkv[(size_t)M_TOTAL * QKV_N];   // ~462 MB
__device__ float g_att[(size_t)M_TOTAL * C_DIM];   // ~154 MB

// ---------------------------------------------------------------------------
// Generic fp32 tiled GEMM: C[M,N] = A[M,K] @ B[K,N] (+ bias[N])
// BM=128, BN=64, BK=16, 256 threads, 8x4 register tile per thread.
// Requires: M % 128 == 0, N % 64 == 0, K % 16 == 0 (true for all our shapes).
// ---------------------------------------------------------------------------
#define BM 128
#define BN 64
#define BK 16
#define TM 8
#define TN 4

__global__ __launch_bounds__(256)
void gemm_kernel(const float* __restrict__ A, const float* __restrict__ Bm,
                 float* __restrict__ Cm, const float* __restrict__ bias,
                 int M, int N, int K)
{
    __shared__ __align__(16) float As[BK][BM];   // A transposed tile
    __shared__ __align__(16) float Bs[BK][BN];

    const int tid  = threadIdx.x;          // 0..255
    const int tcol = tid & 15;             // 0..15 -> 4-col group
    const int trow = tid >> 4;             // 0..15 -> 8-row group
    const int m0 = blockIdx.x * BM;
    const int n0 = blockIdx.y * BN;

    float acc[TM][TN];
#pragma unroll
    for (int i = 0; i < TM; i++)
#pragma unroll
        for (int j = 0; j < TN; j++) acc[i][j] = 0.0f;

    for (int k0 = 0; k0 < K; k0 += BK) {
        // Load A tile (BM x BK) transposed into As[BK][BM]: 512 float4s
#pragma unroll
        for (int f = tid; f < BM * BK / 4; f += 256) {
            int m  = f >> 2;           // 0..127
            int kq = f & 3;            // 0..3 (float4 group along K)
            const float4 a4 = *reinterpret_cast<const float4*>(
                A + (size_t)(m0 + m) * K + k0 + kq * 4);
            As[kq * 4 + 0][m] = a4.x;
            As[kq * 4 + 1][m] = a4.y;
            As[kq * 4 + 2][m] = a4.z;
            As[kq * 4 + 3][m] = a4.w;
        }
        // Load B tile (BK x BN): 256 float4s
        {
            int f = tid;               // 0..255 exactly covers 16x16 float4s
            int kr = f >> 4;           // 0..15
            int nq = f & 15;           // 0..15
            const float4 b4 = *reinterpret_cast<const float4*>(
                Bm + (size_t)(k0 + kr) * N + n0 + nq * 4);
            *reinterpret_cast<float4*>(&Bs[kr][nq * 4]) = b4;
        }
        __syncthreads();

#pragma unroll
        for (int kk = 0; kk < BK; kk++) {
            float a[TM], b[TN];
            const float4 a0 = *reinterpret_cast<const float4*>(&As[kk][trow * TM + 0]);
            const float4 a1 = *reinterpret_cast<const float4*>(&As[kk][trow * TM + 4]);
            a[0]=a0.x; a[1]=a0.y; a[2]=a0.z; a[3]=a0.w;
            a[4]=a1.x; a[5]=a1.y; a[6]=a1.z; a[7]=a1.w;
            const float4 b0 = *reinterpret_cast<const float4*>(&Bs[kk][tcol * TN]);
            b[0]=b0.x; b[1]=b0.y; b[2]=b0.z; b[3]=b0.w;
#pragma unroll
            for (int i = 0; i < TM; i++)
#pragma unroll
                for (int j = 0; j < TN; j++)
                    acc[i][j] = fmaf(a[i], b[j], acc[i][j]);
        }
        __syncthreads();
    }

    // Epilogue
    float4 bv = make_float4(0.f, 0.f, 0.f, 0.f);
    if (bias) bv = *reinterpret_cast<const float4*>(bias + n0 + tcol * TN);
#pragma unroll
    for (int i = 0; i < TM; i++) {
        const int row = m0 + trow * TM + i;
        float4 o;
        o.x = acc[i][0] + bv.x;
        o.y = acc[i][1] + bv.y;
        o.z = acc[i][2] + bv.z;
        o.w = acc[i][3] + bv.w;
        *reinterpret_cast<float4*>(Cm + (size_t)row * N + n0 + tcol * TN) = o;
    }
}

// ---------------------------------------------------------------------------
// Fused attention: one block per (window b, head h).
//   q,k,v from g_qkv; S = q k^T * scale + mask[b % 64]; softmax; O = P v
// ---------------------------------------------------------------------------
__global__ __launch_bounds__(128)
void attn_kernel(const float* __restrict__ mask)
{
    __shared__ float qs[NTOK][DHEAD + 1];
    __shared__ float ks[NTOK][DHEAD + 1];
    __shared__ float vs[NTOK][DHEAD];
    __shared__ float ss[NTOK][NTOK];

    const int blk = blockIdx.x;
    const int b = blk / NHEAD;
    const int h = blk % NHEAD;
    const int tid = threadIdx.x;           // 128 threads
    const float scale = 0.17677669529663687f;   // 32^{-1/2}

    const size_t base = (size_t)b * NTOK * QKV_N;
    const int qc = h * DHEAD;
    const int kc = C_DIM + h * DHEAD;
    const int vc = 2 * C_DIM + h * DHEAD;

    // Load q (pre-scaled), k, v
    for (int e = tid; e < NTOK * DHEAD; e += 128) {
        const int i = e >> 5, d = e & 31;
        const float* row = g_qkv + base + (size_t)i * QKV_N;
        qs[i][d] = row[qc + d] * scale;
        ks[i][d] = row[kc + d];
        vs[i][d] = row[vc + d];
    }
    __syncthreads();

    // S = q k^T + mask   (16 threads per row, 8 rows in flight)
    const float* mrow = mask + (size_t)(b & (NWIN - 1)) * NTOK * NTOK;
    const int lane16 = tid & 15;
    const int rgrp   = tid >> 4;
    for (int i = rgrp; i < NTOK; i += 8) {
        const int j0 = lane16, j1 = lane16 + 16, j2 = lane16 + 32;
        float a0 = 0.f, a1 = 0.f, a2 = 0.f, a3 = 0.f;
#pragma unroll
        for (int d = 0; d < DHEAD; d++) {
            const float qv = qs[i][d];
            a0 = fmaf(qv, ks[j0][d], a0);
            a1 = fmaf(qv, ks[j1][d], a1);
            a2 = fmaf(qv, ks[j2][d], a2);
            a3 = fmaf(qv, ks[48][d], a3);      // column 48, redundant across lanes
        }
        ss[i][j0] = a0 + mrow[i * NTOK + j0];
        ss[i][j1] = a1 + mrow[i * NTOK + j1];
        ss[i][j2] = a2 + mrow[i * NTOK + j2];
        if (lane16 == 0) ss[i][48] = a3 + mrow[i * NTOK + 48];
    }
    __syncthreads();

    // Row softmax (threads 0..48, each one full row)
    if (tid < NTOK) {
        float mx = -1e30f;
#pragma unroll
        for (int j = 0; j < NTOK; j++) mx = fmaxf(mx, ss[tid][j]);
        float sum = 0.f;
#pragma unroll
        for (int j = 0; j < NTOK; j++) {
            const float e = __expf(ss[tid][j] - mx);
            ss[tid][j] = e;
            sum += e;
        }
        const float inv = 1.0f / sum;
#pragma unroll
        for (int j = 0; j < NTOK; j++) ss[tid][j] *= inv;
    }
    __syncthreads();

    // O = P V  -> g_att[b, i, h*32 + d]
    for (int e = tid; e < NTOK * DHEAD; e += 128) {
        const int i = e >> 5, d = e & 31;
        float acc = 0.f;
#pragma unroll
        for (int j = 0; j < NTOK; j++)
            acc = fmaf(ss[i][j], vs[j][d], acc);
        g_att[(size_t)(b * NTOK + i) * C_DIM + h * DHEAD + d] = acc;
    }
}

// ---------------------------------------------------------------------------
// Launch: QKV GEMM -> attention -> projection GEMM (+bias)
// ---------------------------------------------------------------------------
extern "C" void kernel_launch(void* const* d_in, const int* in_sizes, int n_in,
                              void* d_out, int out_size)
{
    const float* x      = (const float*)d_in[0];
    const float* mask   = (const float*)d_in[1];
    const float* w_qkv  = (const float*)d_in[2];
    const float* w_proj = (const float*)d_in[3];
    const float* b_proj = (const float*)d_in[4];
    float* out = (float*)d_out;

    float *qkv_ptr, *att_ptr;
    cudaGetSymbolAddress((void**)&qkv_ptr, g_qkv);
    cudaGetSymbolAddress((void**)&att_ptr, g_att);

    // QKV: [200704,192] @ [192,576]
    gemm_kernel<<<dim3(M_TOTAL / BM, QKV_N / BN), 256>>>(
        x, w_qkv, qkv_ptr, nullptr, M_TOTAL, QKV_N, C_DIM);

    // Attention per (window, head)
    attn_kernel<<<B_WIN * NHEAD, 128>>>(mask);

    // Projection: [200704,192] @ [192,192] + bias
    gemm_kernel<<<dim3(M_TOTAL / BM, C_DIM / BN), 256>>>(
        att_ptr, w_proj, out, b_proj, M_TOTAL, C_DIM, C_DIM);
}